// round 5
// baseline (speedup 1.0000x reference)
#include <cuda_runtime.h>
#include <cuda_bf16.h>
#include <cstdint>

// Constants: B=16, C=128, T=8, BR=16, S=8, SY=64, INPUT_SIZE=16384, C*T*BR=16384
// seg_on    = (count of active synapses among 64) >= 16
// branch_on = (count of on segments among 8) >= 4
// Output    = layer2 branch_on at t==0 -> (16, 128, 16) float32
//
// All counting is bit-sliced over 32-bit registers: low 16 bits = batch masks
// of branch b0, high 16 bits = batch masks of branch b1 (dual-branch packing).

__device__ __align__(16) uint8_t  g_xlo[16384];   // batches 0-7 of x[j]
__device__ __align__(16) uint8_t  g_xhi[16384];   // batches 8-15 of x[j]
__device__ __align__(16) uint16_t g_act1[16384];  // layer1 branch_on masks

__device__ __forceinline__ uint32_t maj3(uint32_t a, uint32_t b, uint32_t c) {
    return (a & b) | (a & c) | (b & c);
}

#define SHFLX(v, m) __shfl_xor_sync(0xffffffffu, (v), (m))

// Dual-segment: 8 lanes cooperate; p = this lane's 8 synapses of segment of
// branch b0, q = same for b1. Returns 32-bit dual mask (lo16 = b0's seg>=16,
// hi16 = b1's) on all 8 lanes of the group.
__device__ __forceinline__ uint32_t seg_ge16_dual(const int4* __restrict__ p,
                                                  const int4* __restrict__ q,
                                                  const uint16_t* __restrict__ sx) {
    int4 a = p[0], b = p[1];
    int4 c = q[0], d = q[1];
    uint32_t m0 = sx[a.x + 1] | ((uint32_t)sx[c.x + 1] << 16);
    uint32_t m1 = sx[a.y + 1] | ((uint32_t)sx[c.y + 1] << 16);
    uint32_t m2 = sx[a.z + 1] | ((uint32_t)sx[c.z + 1] << 16);
    uint32_t m3 = sx[a.w + 1] | ((uint32_t)sx[c.w + 1] << 16);
    uint32_t m4 = sx[b.x + 1] | ((uint32_t)sx[d.x + 1] << 16);
    uint32_t m5 = sx[b.y + 1] | ((uint32_t)sx[d.y + 1] << 16);
    uint32_t m6 = sx[b.z + 1] | ((uint32_t)sx[d.z + 1] << 16);
    uint32_t m7 = sx[b.w + 1] | ((uint32_t)sx[d.w + 1] << 16);

    // Wallace-8: sum = w1 + 2*w2 + 4*w4 + 8*w8 per bit lane
    uint32_t s1 = m0 ^ m1 ^ m2, c1 = maj3(m0, m1, m2);
    uint32_t s2 = m3 ^ m4 ^ m5, c2 = maj3(m3, m4, m5);
    uint32_t s3 = s1 ^ s2 ^ m6, c3 = maj3(s1, s2, m6);
    uint32_t w1 = s3 ^ m7,      c4 = s3 & m7;
    uint32_t s4 = c1 ^ c2 ^ c3, c5 = maj3(c1, c2, c3);
    uint32_t w2 = s4 ^ c4,      c6 = s4 & c4;
    uint32_t w4 = c5 ^ c6,      w8 = c5 & c6;

    // level 1 (xor 1): two counts <=8 -> <=16
    uint32_t r0 = SHFLX(w1, 1), r1 = SHFLX(w2, 1), r2 = SHFLX(w4, 1), r3 = SHFLX(w8, 1);
    uint32_t k  = w1 & r0;
    uint32_t t0 = w1 ^ r0;
    uint32_t t1 = w2 ^ r1 ^ k;  k = maj3(w2, r1, k);
    uint32_t t2 = w4 ^ r2 ^ k;  k = maj3(w4, r2, k);
    uint32_t t3 = w8 ^ r3 ^ k;
    uint32_t t4 = maj3(w8, r3, k);

    // level 2 (xor 2): -> <=32
    r0 = SHFLX(t0, 2); r1 = SHFLX(t1, 2); r2 = SHFLX(t2, 2); r3 = SHFLX(t3, 2);
    uint32_t r4 = SHFLX(t4, 2);
    k = t0 & r0;
    uint32_t u0 = t0 ^ r0;
    uint32_t u1 = t1 ^ r1 ^ k;  k = maj3(t1, r1, k);
    uint32_t u2 = t2 ^ r2 ^ k;  k = maj3(t2, r2, k);
    uint32_t u3 = t3 ^ r3 ^ k;  k = maj3(t3, r3, k);
    uint32_t u4 = t4 ^ r4 ^ k;
    uint32_t u5 = maj3(t4, r4, k);

    // level 3 (xor 4): need only (sum >= 16)
    r0 = SHFLX(u0, 4); r1 = SHFLX(u1, 4); r2 = SHFLX(u2, 4); r3 = SHFLX(u3, 4);
    r4 = SHFLX(u4, 4); uint32_t r5 = SHFLX(u5, 4);
    k = u0 & r0;
    k = maj3(u1, r1, k);
    k = maj3(u2, r2, k);
    k = maj3(u3, r3, k);           // carry into bit 4
    return u4 | r4 | k | u5 | r5;
}

// >=4 of 8 one-bit values, per bit lane (works on dual-packed masks)
__device__ __forceinline__ uint32_t branch_ge4(const uint32_t* s) {
    uint32_t o01 = s[0] ^ s[1], t01 = s[0] & s[1];
    uint32_t o23 = s[2] ^ s[3], t23 = s[2] & s[3];
    uint32_t o45 = s[4] ^ s[5], t45 = s[4] & s[5];
    uint32_t o67 = s[6] ^ s[7], t67 = s[6] & s[7];
    uint32_t ca  = o01 & o23;
    uint32_t o03 = o01 ^ o23;
    uint32_t t03 = t01 ^ t23 ^ ca;
    uint32_t f03 = maj3(t01, t23, ca);
    uint32_t cb  = o45 & o67;
    uint32_t o47 = o45 ^ o67;
    uint32_t t47 = t45 ^ t67 ^ cb;
    uint32_t f47 = maj3(t45, t67, cb);
    uint32_t c1 = o03 & o47;
    uint32_t c2 = maj3(t03, t47, c1);
    return f03 | f47 | c2;
}

// Pack x (16 x 16384 floats of {0,1}) into byte planes.
// 128 blocks x 256 threads; blocks 0-63 -> batches 0-7, 64-127 -> 8-15.
__global__ void __launch_bounds__(256) k_pack(const float* __restrict__ x) {
    int half = blockIdx.x >> 6;
    int j = ((blockIdx.x & 63) << 8) + threadIdx.x;
    const float* xp = x + half * 8 * 16384 + j;
    float v[8];
#pragma unroll
    for (int b = 0; b < 8; b++) v[b] = xp[b * 16384];
    uint32_t m = 0;
#pragma unroll
    for (int b = 0; b < 8; b++) m |= (v[b] != 0.0f) ? (1u << b) : 0u;
    (half ? g_xhi : g_xlo)[j] = (uint8_t)m;
}

// Layer 1: 256 blocks x 256 threads; warp covers 8 branches (4 dual pairs).
__global__ void __launch_bounds__(256) k_layer1(const int* __restrict__ idx) {
    __shared__ uint16_t sx[16386];
    __shared__ uint32_t segbuf[8][32];
    if (threadIdx.x == 0) sx[0] = 0;
    {
        const uint32_t* lo32 = reinterpret_cast<const uint32_t*>(g_xlo);
        const uint32_t* hi32 = reinterpret_cast<const uint32_t*>(g_xhi);
        for (int i = threadIdx.x; i < 4096; i += 256) {
            uint32_t lo = lo32[i], hi = hi32[i];
#pragma unroll
            for (int kb = 0; kb < 4; kb++)
                sx[1 + 4 * i + kb] = (uint16_t)(((lo >> (8 * kb)) & 0xFFu) |
                                                (((hi >> (8 * kb)) & 0xFFu) << 8));
        }
    }
    __syncthreads();

    int w = threadIdx.x >> 5, lane = threadIdx.x & 31;
    int pos = lane & 7, sg = lane >> 3;
    int bb = blockIdx.x * 64 + w * 8;            // 8 branches per warp
#pragma unroll
    for (int kk = 0; kk < 8; kk++) {
        int b0 = bb + (kk >> 1) * 2;             // branch pair (b0, b0+1)
        int seg = ((kk & 1) << 2) + sg;
        const int4* p = reinterpret_cast<const int4*>(idx + b0 * 512 + seg * 64 + pos * 8);
        const int4* q = reinterpret_cast<const int4*>(idx + (b0 + 1) * 512 + seg * 64 + pos * 8);
        uint32_t g = seg_ge16_dual(p, q, sx);
        if (pos == 0) segbuf[w][(kk >> 1) * 8 + seg] = g;
    }
    __syncwarp();
    if (lane < 4) {
        uint32_t ge4 = branch_ge4(&segbuf[w][lane * 8]);   // dual result
        g_act1[bb + lane * 2]     = (uint16_t)(ge4 & 0xFFFFu);
        g_act1[bb + lane * 2 + 1] = (uint16_t)(ge4 >> 16);
    }
}

// Layer 2 (t==0 only): 2048 branches; 64 blocks x 256 threads;
// warp covers 4 branches (2 dual pairs).
__global__ void __launch_bounds__(256) k_layer2(const int* __restrict__ idx,
                                                float* __restrict__ out) {
    __shared__ uint16_t sx[16386];
    __shared__ uint32_t segbuf[8][16];
    if (threadIdx.x == 0) sx[0] = 0;
    {
        const uint32_t* src = reinterpret_cast<const uint32_t*>(g_act1);
        for (int i = threadIdx.x; i < 8192; i += 256) {
            uint32_t v = src[i];
            sx[1 + 2 * i] = (uint16_t)(v & 0xFFFFu);
            sx[2 + 2 * i] = (uint16_t)(v >> 16);
        }
    }
    __syncthreads();

    int w = threadIdx.x >> 5, lane = threadIdx.x & 31;
    int pos = lane & 7, sg = lane >> 3;
    int pb = blockIdx.x * 32 + w * 4;            // 4 branches per warp
#pragma unroll
    for (int kk = 0; kk < 4; kk++) {
        int b0 = pb + (kk >> 1) * 2;             // global branch = c*16 + br
        int b1 = b0 + 1;
        int seg = ((kk & 1) << 2) + sg;
        int c0 = b0 >> 4, br0 = b0 & 15;
        int c1 = b1 >> 4, br1 = b1 & 15;
        // idx2 flat offset of (c, t=0, br, seg, pos*8)
        const int4* p = reinterpret_cast<const int4*>(
            idx + (c0 * 1024 + br0 * 8 + seg) * 64 + pos * 8);
        const int4* q = reinterpret_cast<const int4*>(
            idx + (c1 * 1024 + br1 * 8 + seg) * 64 + pos * 8);
        uint32_t g = seg_ge16_dual(p, q, sx);
        if (pos == 0) segbuf[w][(kk >> 1) * 8 + seg] = g;
    }
    __syncwarp();
    if (lane < 2) {
        uint32_t ge4 = branch_ge4(&segbuf[w][lane * 8]);
        int prA = pb + lane * 2, prB = prA + 1;
        int cA = prA >> 4, brA = prA & 15;
        int cB = prB >> 4, brB = prB & 15;
#pragma unroll
        for (int b = 0; b < 16; b++) {
            out[(b * 128 + cA) * 16 + brA] = ((ge4 >> b) & 1u) ? 1.0f : 0.0f;
            out[(b * 128 + cB) * 16 + brB] = ((ge4 >> (16 + b)) & 1u) ? 1.0f : 0.0f;
        }
    }
}

extern "C" void kernel_launch(void* const* d_in, const int* in_sizes, int n_in,
                              void* d_out, int out_size) {
    const float* x = nullptr;
    const int* idxA = nullptr;
    const int* idxB = nullptr;
    for (int i = 0; i < n_in; i++) {
        if (in_sizes[i] == 262144 && !x) {
            x = (const float*)d_in[i];
        } else if (!idxA) {
            idxA = (const int*)d_in[i];
        } else if (!idxB) {
            idxB = (const int*)d_in[i];
        }
    }
    if (!x) { x = (const float*)d_in[0]; idxA = (const int*)d_in[1]; idxB = (const int*)d_in[2]; }

    float* out = (float*)d_out;   // (16, 128, 16) float32

    k_pack  <<<128, 256>>>(x);
    k_layer1<<<256, 256>>>(idxA);
    k_layer2<<<64, 256>>>(idxB, out);
}

// round 6
// speedup vs baseline: 1.0077x; 1.0077x over previous
#include <cuda_runtime.h>
#include <cuda_bf16.h>
#include <cstdint>

// Constants: B=16, C=128, T=8, BR=16, S=8, SY=64, INPUT_SIZE=16384, C*T*BR=16384
// seg_on = (count>=16 of 64), branch_on = (count>=4 of 8)
// Output = layer2 branch_on at t==0 -> (16,128,16) float32

#define NB 256   // persistent blocks; all co-resident in wave 1 (33KB smem -> 6 blocks/SM cap)

__device__ __align__(16) uint16_t g_xbits[16384];
__device__ __align__(16) uint16_t g_act1[16384];
__device__ unsigned g_count = 0;
__device__ unsigned g_gen   = 0;

__device__ __forceinline__ uint32_t maj3(uint32_t a, uint32_t b, uint32_t c) {
    return (a & b) | (a & c) | (b & c);
}

#define SHFLX(v, m) __shfl_xor_sync(0xffffffffu, (v), (m))

// Software grid barrier (sense-reversal; g_count self-resets -> replay-safe).
__device__ __forceinline__ void grid_barrier() {
    __threadfence();
    __syncthreads();
    if (threadIdx.x == 0) {
        unsigned gen = *(volatile unsigned*)&g_gen;
        if (atomicAdd(&g_count, 1u) == NB - 1u) {
            atomicExch(&g_count, 0u);
            __threadfence();
            atomicAdd(&g_gen, 1u);
        } else {
            while (*(volatile unsigned*)&g_gen == gen) { }
        }
    }
    __syncthreads();
    __threadfence();
}

// 8 lanes cooperate on one 64-synapse segment; returns on all 8 lanes the
// 16-bit batch mask of (segment count >= 16). [identical to R4 - proven]
__device__ __forceinline__ uint32_t seg_ge16_warp(const int4* __restrict__ p,
                                                  const uint16_t* __restrict__ sx) {
    int4 a = p[0];
    int4 b = p[1];
    uint32_t m0 = sx[a.x + 1], m1 = sx[a.y + 1], m2 = sx[a.z + 1], m3 = sx[a.w + 1];
    uint32_t m4 = sx[b.x + 1], m5 = sx[b.y + 1], m6 = sx[b.z + 1], m7 = sx[b.w + 1];

    uint32_t s1 = m0 ^ m1 ^ m2, c1 = maj3(m0, m1, m2);
    uint32_t s2 = m3 ^ m4 ^ m5, c2 = maj3(m3, m4, m5);
    uint32_t s3 = s1 ^ s2 ^ m6, c3 = maj3(s1, s2, m6);
    uint32_t w1 = s3 ^ m7,      c4 = s3 & m7;
    uint32_t s4 = c1 ^ c2 ^ c3, c5 = maj3(c1, c2, c3);
    uint32_t w2 = s4 ^ c4,      c6 = s4 & c4;
    uint32_t w4 = c5 ^ c6,      w8 = c5 & c6;

    uint32_t r0 = SHFLX(w1, 1), r1 = SHFLX(w2, 1), r2 = SHFLX(w4, 1), r3 = SHFLX(w8, 1);
    uint32_t k  = w1 & r0;
    uint32_t t0 = w1 ^ r0;
    uint32_t t1 = w2 ^ r1 ^ k;  k = maj3(w2, r1, k);
    uint32_t t2 = w4 ^ r2 ^ k;  k = maj3(w4, r2, k);
    uint32_t t3 = w8 ^ r3 ^ k;
    uint32_t t4 = maj3(w8, r3, k);

    r0 = SHFLX(t0, 2); r1 = SHFLX(t1, 2); r2 = SHFLX(t2, 2); r3 = SHFLX(t3, 2);
    uint32_t r4 = SHFLX(t4, 2);
    k = t0 & r0;
    uint32_t u0 = t0 ^ r0;
    uint32_t u1 = t1 ^ r1 ^ k;  k = maj3(t1, r1, k);
    uint32_t u2 = t2 ^ r2 ^ k;  k = maj3(t2, r2, k);
    uint32_t u3 = t3 ^ r3 ^ k;  k = maj3(t3, r3, k);
    uint32_t u4 = t4 ^ r4 ^ k;
    uint32_t u5 = maj3(t4, r4, k);

    r0 = SHFLX(u0, 4); r1 = SHFLX(u1, 4); r2 = SHFLX(u2, 4); r3 = SHFLX(u3, 4);
    r4 = SHFLX(u4, 4); uint32_t r5 = SHFLX(u5, 4);
    k = u0 & r0;
    k = maj3(u1, r1, k);
    k = maj3(u2, r2, k);
    k = maj3(u3, r3, k);
    return u4 | r4 | k | u5 | r5;
}

__device__ __forceinline__ uint32_t branch_ge4(const uint32_t* s) {
    uint32_t o01 = s[0] ^ s[1], t01 = s[0] & s[1];
    uint32_t o23 = s[2] ^ s[3], t23 = s[2] & s[3];
    uint32_t o45 = s[4] ^ s[5], t45 = s[4] & s[5];
    uint32_t o67 = s[6] ^ s[7], t67 = s[6] & s[7];
    uint32_t ca  = o01 & o23;
    uint32_t o03 = o01 ^ o23;
    uint32_t t03 = t01 ^ t23 ^ ca;
    uint32_t f03 = maj3(t01, t23, ca);
    uint32_t cb  = o45 & o67;
    uint32_t o47 = o45 ^ o67;
    uint32_t t47 = t45 ^ t67 ^ cb;
    uint32_t f47 = maj3(t45, t67, cb);
    uint32_t c1 = o03 & o47;
    uint32_t c2 = maj3(t03, t47, c1);
    return f03 | f47 | c2;
}

__device__ __forceinline__ void fill_table(uint16_t* sx, const uint16_t* gtab) {
    if (threadIdx.x == 0) sx[0] = 0;
    const uint32_t* src = reinterpret_cast<const uint32_t*>(gtab);
    for (int i = threadIdx.x; i < 8192; i += 256) {
        uint32_t v = src[i];
        sx[1 + 2 * i] = (uint16_t)(v & 0xFFFFu);
        sx[2 + 2 * i] = (uint16_t)(v >> 16);
    }
    __syncthreads();
}

__global__ void __launch_bounds__(256) k_all(const float* __restrict__ x,
                                             const int* __restrict__ idx1,
                                             const int* __restrict__ idx2,
                                             float* __restrict__ out) {
    __shared__ uint16_t sx[16386];
    __shared__ uint32_t segbuf[8][32];

    int tid = threadIdx.x;
    int w = tid >> 5, lane = tid & 31;
    int pos = lane & 7, sg = lane >> 3;

    // ---- Phase A: pack x into 16-bit batch masks ----
    {
        int j = blockIdx.x * 256 + tid;
        if (j < 16384) {
            uint32_t m = 0;
#pragma unroll
            for (int b = 0; b < 16; b++)
                m |= (x[b * 16384 + j] != 0.0f) ? (1u << b) : 0u;
            g_xbits[j] = (uint16_t)m;
        }
    }
    grid_barrier();

    // ---- Phase B: layer 1 over 16384 branches ----
    fill_table(sx, g_xbits);
    {
        int warpGlobal = blockIdx.x * 8 + w;        // 0..2047
#pragma unroll
        for (int uu = 0; uu < 2; uu++) {
            int unit = warpGlobal + uu * 2048;      // 0..4095, 4 branches each
            int bb = unit * 4;
#pragma unroll
            for (int kk = 0; kk < 8; kk++) {
                int branch = bb + (kk >> 1);
                int seg = ((kk & 1) << 2) + sg;
                const int4* p = reinterpret_cast<const int4*>(
                    idx1 + branch * 512 + seg * 64 + pos * 8);
                uint32_t g = seg_ge16_warp(p, sx);
                if (pos == 0) segbuf[w][(kk >> 1) * 8 + seg] = g;
            }
            __syncwarp();
            if (lane < 4) {
                uint32_t ge4 = branch_ge4(&segbuf[w][lane * 8]);
                g_act1[bb + lane] = (uint16_t)ge4;
            }
            __syncwarp();
        }
    }
    grid_barrier();

    // ---- Phase C: layer 2 (t == 0 only), blocks 0..63 ----
    if (blockIdx.x < 64) {
        fill_table(sx, g_act1);
        int unit = blockIdx.x * 8 + w;              // 0..511, 4 branches each
        int pb = unit * 4;
#pragma unroll
        for (int kk = 0; kk < 8; kk++) {
            int pr = pb + (kk >> 1);                // branch id = c*16 + br
            int c = pr >> 4, br = pr & 15;
            int seg = ((kk & 1) << 2) + sg;
            const int4* p = reinterpret_cast<const int4*>(
                idx2 + (c * 1024 + br * 8 + seg) * 64 + pos * 8);
            uint32_t g = seg_ge16_warp(p, sx);
            if (pos == 0) segbuf[w][(kk >> 1) * 8 + seg] = g;
        }
        __syncwarp();
        if (lane < 4) {
            uint32_t ge4 = branch_ge4(&segbuf[w][lane * 8]);
            int pr = pb + lane;
            int c = pr >> 4, br = pr & 15;
#pragma unroll
            for (int b = 0; b < 16; b++)
                out[(b * 128 + c) * 16 + br] = ((ge4 >> b) & 1u) ? 1.0f : 0.0f;
        }
    }
}

extern "C" void kernel_launch(void* const* d_in, const int* in_sizes, int n_in,
                              void* d_out, int out_size) {
    const float* x = nullptr;
    const int* idxA = nullptr;
    const int* idxB = nullptr;
    for (int i = 0; i < n_in; i++) {
        if (in_sizes[i] == 262144 && !x) {
            x = (const float*)d_in[i];
        } else if (!idxA) {
            idxA = (const int*)d_in[i];
        } else if (!idxB) {
            idxB = (const int*)d_in[i];
        }
    }
    if (!x) { x = (const float*)d_in[0]; idxA = (const int*)d_in[1]; idxB = (const int*)d_in[2]; }

    float* out = (float*)d_out;   // (16, 128, 16) float32

    k_all<<<NB, 256>>>(x, idxA, idxB, out);
}